// round 3
// baseline (speedup 1.0000x reference)
#include <cuda_runtime.h>
#include <math.h>

#define MAXN 50000
#define MAXE 800000
#define MAXET (MAXE + MAXN)

// ---------------- static scratch (no allocation allowed) ----------------
__device__ float g_h0[MAXN * 128];     // encoder output
__device__ float g_h1[MAXN * 128];     // layer1 output
__device__ float g_h2[MAXN * 128];     // layer2 output
__device__ float g_xlr[MAXN * 256];    // xl | xr, row stride 256
__device__ float g_t[MAXN * 128];      // relu(h2@W1+b1)
__device__ float g_denom[MAXN * 4];    // per-node per-head softmax denominator
__device__ int   g_deg[MAXN];
__device__ int   g_rowptr[MAXN + 1];
__device__ int   g_cursor[MAXN];
__device__ int   g_csr_src[MAXET];
__device__ int   g_csr_eid[MAXET];
__device__ float g_alpha_fb[MAXET * 4];   // fallback alpha buffer if out layout unexpected

// ---------------- CSR construction ----------------
__global__ void zero_deg(int N) {
    int i = blockIdx.x * blockDim.x + threadIdx.x;
    if (i < N) g_deg[i] = 0;
}

__global__ void build_deg(const int* __restrict__ ei, int E, int Etot) {
    int e = blockIdx.x * blockDim.x + threadIdx.x;
    if (e >= Etot) return;
    int dst = (e < E) ? ei[E + e] : (e - E);
    atomicAdd(&g_deg[dst], 1);
}

// single-block exclusive scan: g_deg -> g_rowptr (+cursor copy), g_rowptr[N]=total
__global__ void scan_kernel(int N) {
    __shared__ int wsum[32];
    __shared__ int s_carry;
    int lane = threadIdx.x & 31;
    int wid  = threadIdx.x >> 5;
    if (threadIdx.x == 0) s_carry = 0;
    __syncthreads();
    for (int base = 0; base < N; base += 1024) {
        int i = base + threadIdx.x;
        int v = (i < N) ? g_deg[i] : 0;
        // warp inclusive scan
        int x = v;
        #pragma unroll
        for (int off = 1; off < 32; off <<= 1) {
            int y = __shfl_up_sync(0xffffffffu, x, off);
            if (lane >= off) x += y;
        }
        if (lane == 31) wsum[wid] = x;
        __syncthreads();
        if (wid == 0) {
            int w = wsum[lane];
            #pragma unroll
            for (int off = 1; off < 32; off <<= 1) {
                int y = __shfl_up_sync(0xffffffffu, w, off);
                if (lane >= off) w += y;
            }
            wsum[lane] = w;
        }
        __syncthreads();
        int incl  = x + (wid > 0 ? wsum[wid - 1] : 0);
        int total = wsum[31];
        int excl  = incl - v + s_carry;
        if (i < N) { g_rowptr[i] = excl; g_cursor[i] = excl; }
        __syncthreads();
        if (threadIdx.x == 0) s_carry += total;
        __syncthreads();
    }
    if (threadIdx.x == 0) g_rowptr[N] = s_carry;
}

__global__ void scatter_edges(const int* __restrict__ ei, int E, int Etot) {
    int e = blockIdx.x * blockDim.x + threadIdx.x;
    if (e >= Etot) return;
    int src, dst;
    if (e < E) { src = ei[e]; dst = ei[E + e]; }
    else       { src = dst = e - E; }
    int pos = atomicAdd(&g_cursor[dst], 1);
    g_csr_src[pos] = src;
    g_csr_eid[pos] = e;
}

// ---------------- encoder: h0 = x @ W(16x128) + b ----------------
__global__ void encoder_kernel(const float* __restrict__ x,
                               const float* __restrict__ W,
                               const float* __restrict__ b, int N) {
    int n = blockIdx.x;
    if (n >= N) return;
    int t = threadIdx.x;  // 128 threads
    __shared__ float xs[16];
    if (t < 16) xs[t] = x[n * 16 + t];
    __syncthreads();
    float acc = b[t];
    #pragma unroll
    for (int k = 0; k < 16; k++) acc = fmaf(xs[k], W[k * 128 + t], acc);
    g_h0[n * 128 + t] = acc;
}

// ---------------- tiled SGEMM: C[M,128] = A[M,128] @ B[128,128] + bias ----------------
template <int RELU>
__global__ __launch_bounds__(256) void sgemm_k128(
    const float* __restrict__ A, int lda,
    const float* __restrict__ B,
    const float* __restrict__ bias,
    float* __restrict__ C, int ldc, int M)
{
    __shared__ float As[8][128];
    __shared__ float Bs[8][128];
    int tid = threadIdx.x;
    int m0  = blockIdx.x * 128;
    int tx = tid & 15, ty = tid >> 4;
    int cm = ty * 8, cn = tx * 8;

    float acc[8][8];
    #pragma unroll
    for (int i = 0; i < 8; i++)
        #pragma unroll
        for (int j = 0; j < 8; j++) acc[i][j] = 0.f;

    int arow = tid >> 1;
    int acol = (tid & 1) * 4;
    int brow = tid >> 5;
    int bcol = (tid & 31) * 4;

    for (int k0 = 0; k0 < 128; k0 += 8) {
        float4 av = make_float4(0.f, 0.f, 0.f, 0.f);
        if (m0 + arow < M)
            av = *(const float4*)(A + (size_t)(m0 + arow) * lda + k0 + acol);
        As[acol + 0][arow] = av.x;
        As[acol + 1][arow] = av.y;
        As[acol + 2][arow] = av.z;
        As[acol + 3][arow] = av.w;
        float4 bv = *(const float4*)(B + (k0 + brow) * 128 + bcol);
        *(float4*)(&Bs[brow][bcol]) = bv;
        __syncthreads();
        #pragma unroll
        for (int k = 0; k < 8; k++) {
            float a[8], b[8];
            #pragma unroll
            for (int i = 0; i < 8; i++) a[i] = As[k][cm + i];
            #pragma unroll
            for (int j = 0; j < 8; j++) b[j] = Bs[k][cn + j];
            #pragma unroll
            for (int i = 0; i < 8; i++)
                #pragma unroll
                for (int j = 0; j < 8; j++) acc[i][j] = fmaf(a[i], b[j], acc[i][j]);
        }
        __syncthreads();
    }

    #pragma unroll
    for (int i = 0; i < 8; i++) {
        int m = m0 + cm + i;
        if (m < M) {
            #pragma unroll
            for (int j = 0; j < 8; j += 4) {
                float4 o;
                o.x = acc[i][j + 0] + bias[cn + j + 0];
                o.y = acc[i][j + 1] + bias[cn + j + 1];
                o.z = acc[i][j + 2] + bias[cn + j + 2];
                o.w = acc[i][j + 3] + bias[cn + j + 3];
                if (RELU) {
                    o.x = fmaxf(o.x, 0.f); o.y = fmaxf(o.y, 0.f);
                    o.z = fmaxf(o.z, 0.f); o.w = fmaxf(o.w, 0.f);
                }
                *(float4*)(C + (size_t)m * ldc + cn + j) = o;
            }
        }
    }
}

// ---------------- GATv2 aggregation: one warp per destination node ----------------
// xlr: [N,256] = xl|xr. For each in-edge: s_h = sum_c lrelu(xl+xr)*att; ex = exp(s);
// acc += ex*xl; D += ex. out = acc/D + bo (opt relu). Raw ex -> alpha buffer.
__global__ void gat_aggregate(const float* __restrict__ xlr,
                              const float* __restrict__ att,  // [4*32]
                              const float* __restrict__ bo,   // [128]
                              float* __restrict__ hout,       // [N,128]
                              float* __restrict__ alpha,      // [Etot,4] (raw ex)
                              int N, int do_relu)
{
    int warp = (blockIdx.x * blockDim.x + threadIdx.x) >> 5;
    int lane = threadIdx.x & 31;
    if (warp >= N) return;
    int n = warp;

    float xr_[4], at_[4];
    #pragma unroll
    for (int h = 0; h < 4; h++) {
        xr_[h] = xlr[(size_t)n * 256 + 128 + h * 32 + lane];
        at_[h] = att[h * 32 + lane];
    }
    float acc[4] = {0.f, 0.f, 0.f, 0.f};
    float D[4]   = {0.f, 0.f, 0.f, 0.f};

    int beg = g_rowptr[n], end = g_rowptr[n + 1];
    for (int i = beg; i < end; i++) {
        int src = g_csr_src[i];
        int eid = g_csr_eid[i];
        const float* xlrow = xlr + (size_t)src * 256;
        float xv[4], s[4];
        #pragma unroll
        for (int h = 0; h < 4; h++) {
            xv[h] = xlrow[h * 32 + lane];
            float e = xv[h] + xr_[h];
            e = (e > 0.f) ? e : 0.2f * e;   // leaky_relu(0.2)
            s[h] = e * at_[h];
        }
        #pragma unroll
        for (int off = 16; off > 0; off >>= 1) {
            #pragma unroll
            for (int h = 0; h < 4; h++)
                s[h] += __shfl_xor_sync(0xffffffffu, s[h], off);
        }
        float ex[4];
        #pragma unroll
        for (int h = 0; h < 4; h++) {
            ex[h] = __expf(s[h]);          // scores << 1 -> max-subtraction unnecessary
            D[h] += ex[h];
            acc[h] = fmaf(ex[h], xv[h], acc[h]);
        }
        if (lane == 0) {
            float4 v = make_float4(ex[0], ex[1], ex[2], ex[3]);
            *(float4*)(alpha + (size_t)eid * 4) = v;
        }
    }
    if (lane == 0)
        *(float4*)(g_denom + (size_t)n * 4) = make_float4(D[0], D[1], D[2], D[3]);
    #pragma unroll
    for (int h = 0; h < 4; h++) {
        float o = acc[h] / D[h] + bo[h * 32 + lane];
        if (do_relu) o = fmaxf(o, 0.f);
        hout[(size_t)n * 128 + h * 32 + lane] = o;
    }
}

__global__ void normalize_alpha(const int* __restrict__ ei,
                                float* __restrict__ alpha, int E, int Etot)
{
    int e = blockIdx.x * blockDim.x + threadIdx.x;
    if (e >= Etot) return;
    int dst = (e < E) ? ei[E + e] : (e - E);
    float4 a = *(float4*)(alpha + (size_t)e * 4);
    float4 d = *(const float4*)(g_denom + (size_t)dst * 4);
    a.x /= d.x; a.y /= d.y; a.z /= d.z; a.w /= d.w;
    *(float4*)(alpha + (size_t)e * 4) = a;
}

// ---------------- final: probs = sigmoid(t @ W2 + b2), warp per node ----------------
__global__ void final_kernel(const float* __restrict__ t,
                             const float* __restrict__ W2,
                             const float* __restrict__ b2,
                             float* __restrict__ probs, int N)
{
    int warp = (blockIdx.x * blockDim.x + threadIdx.x) >> 5;
    int lane = threadIdx.x & 31;
    if (warp >= N) return;
    const float* row = t + (size_t)warp * 128;
    float s = 0.f;
    #pragma unroll
    for (int j = 0; j < 4; j++)
        s = fmaf(row[j * 32 + lane], W2[j * 32 + lane], s);
    #pragma unroll
    for (int off = 16; off > 0; off >>= 1)
        s += __shfl_xor_sync(0xffffffffu, s, off);
    if (lane == 0) {
        float logit = s + b2[0];
        probs[warp] = 1.f / (1.f + __expf(-logit));
    }
}

// ---------------- launch ----------------
extern "C" void kernel_launch(void* const* d_in, const int* in_sizes, int n_in,
                              void* d_out, int out_size)
{
    const float* x      = (const float*)d_in[0];
    const int*   ei     = (const int*)  d_in[1];
    const float* enc_W  = (const float*)d_in[4];
    const float* enc_b  = (const float*)d_in[5];
    const float* g1_Wl  = (const float*)d_in[6];
    const float* g1_bl  = (const float*)d_in[7];
    const float* g1_Wr  = (const float*)d_in[8];
    const float* g1_br  = (const float*)d_in[9];
    const float* g1_att = (const float*)d_in[10];
    const float* g1_bo  = (const float*)d_in[11];
    const float* g2_Wl  = (const float*)d_in[12];
    const float* g2_bl  = (const float*)d_in[13];
    const float* g2_Wr  = (const float*)d_in[14];
    const float* g2_br  = (const float*)d_in[15];
    const float* g2_att = (const float*)d_in[16];
    const float* g2_bo  = (const float*)d_in[17];
    const float* mlp_W1 = (const float*)d_in[18];
    const float* mlp_b1 = (const float*)d_in[19];
    const float* mlp_W2 = (const float*)d_in[20];
    const float* mlp_b2 = (const float*)d_in[21];

    int N    = in_sizes[0] / 16;
    int E    = in_sizes[1] / 2;
    int Etot = E + N;

    float *h0, *h1, *h2, *xlr, *tb, *fb;
    cudaGetSymbolAddress((void**)&h0,  g_h0);
    cudaGetSymbolAddress((void**)&h1,  g_h1);
    cudaGetSymbolAddress((void**)&h2,  g_h2);
    cudaGetSymbolAddress((void**)&xlr, g_xlr);
    cudaGetSymbolAddress((void**)&tb,  g_t);
    cudaGetSymbolAddress((void**)&fb,  g_alpha_fb);

    float* probs = (float*)d_out;
    float* alpha1;
    float* alpha2;
    if (out_size >= N + 8 * Etot) {
        alpha1 = probs + N;
        alpha2 = alpha1 + (size_t)4 * Etot;
    } else {
        alpha1 = fb;
        alpha2 = fb;
    }

    int eb = (Etot + 255) / 256;
    int nb = (N + 255) / 256;
    int wb = (N * 32 + 255) / 256;  // warp-per-node grids
    dim3 gg((N + 127) / 128);

    // CSR build (identical every replay, required for determinism of the graph)
    zero_deg<<<nb, 256>>>(N);
    build_deg<<<eb, 256>>>(ei, E, Etot);
    scan_kernel<<<1, 1024>>>(N);
    scatter_edges<<<eb, 256>>>(ei, E, Etot);

    // encoder
    encoder_kernel<<<N, 128>>>(x, enc_W, enc_b, N);

    // GAT layer 1
    sgemm_k128<0><<<gg, 256>>>(h0, 128, g1_Wl, g1_bl, xlr, 256, N);
    sgemm_k128<0><<<gg, 256>>>(h0, 128, g1_Wr, g1_br, xlr + 128, 256, N);
    gat_aggregate<<<wb, 256>>>(xlr, g1_att, g1_bo, h1, alpha1, N, 1);
    normalize_alpha<<<eb, 256>>>(ei, alpha1, E, Etot);

    // GAT layer 2
    sgemm_k128<0><<<gg, 256>>>(h1, 128, g2_Wl, g2_bl, xlr, 256, N);
    sgemm_k128<0><<<gg, 256>>>(h1, 128, g2_Wr, g2_br, xlr + 128, 256, N);
    gat_aggregate<<<wb, 256>>>(xlr, g2_att, g2_bo, h2, alpha2, N, 0);
    normalize_alpha<<<eb, 256>>>(ei, alpha2, E, Etot);

    // MLP head
    sgemm_k128<1><<<gg, 256>>>(h2, 128, mlp_W1, mlp_b1, tb, 128, N);
    final_kernel<<<wb, 256>>>(tb, mlp_W2, mlp_b2, probs, N);
}

// round 4
// speedup vs baseline: 1.2605x; 1.2605x over previous
#include <cuda_runtime.h>
#include <math.h>

#define MAXN 50000
#define MAXE 800000
#define MAXET (MAXE + MAXN)

// ---------------- static scratch (no allocation allowed) ----------------
__device__ float g_h0[MAXN * 128];     // encoder output
__device__ float g_h1[MAXN * 128];     // layer1 output
__device__ float g_h2[MAXN * 128];     // layer2 output
__device__ float g_xlr[MAXN * 256];    // xl | xr, row stride 256
__device__ float g_t[MAXN * 128];      // relu(h2@W1+b1)
__device__ float g_denom[MAXN * 4];    // per-node per-head softmax denominator
__device__ int   g_deg[MAXN];
__device__ int   g_rowptr[MAXN + 1];
__device__ int   g_cursor[MAXN];
__device__ int   g_bsum[64];
__device__ int   g_csr_src[MAXET];
__device__ int   g_csr_eid[MAXET];
__device__ float g_alpha_fb[MAXET * 4];   // fallback alpha buffer if out layout unexpected

// ---------------- f32x2 packed helpers (sm_103a FFMA2) ----------------
__device__ __forceinline__ void ffma2(unsigned long long& d,
                                      unsigned long long a,
                                      unsigned long long b) {
    asm("fma.rn.f32x2 %0, %1, %2, %3;" : "=l"(d) : "l"(a), "l"(b), "l"(d));
}
__device__ __forceinline__ float2 unpack2(unsigned long long v) {
    float2 f;
    asm("mov.b64 {%0,%1}, %2;" : "=f"(f.x), "=f"(f.y) : "l"(v));
    return f;
}

// ---------------- CSR construction ----------------
__global__ void build_deg(const int* __restrict__ ei, int E, int Etot) {
    int e = blockIdx.x * blockDim.x + threadIdx.x;
    if (e >= Etot) return;
    int dst = (e < E) ? ei[E + e] : (e - E);
    atomicAdd(&g_deg[dst], 1);
}

// phase 1: per-block exclusive scan of g_deg -> g_rowptr (in-block), block sums -> g_bsum
__global__ void scan_blocks(int N) {
    __shared__ int wsum[32];
    int i = blockIdx.x * 1024 + threadIdx.x;
    int lane = threadIdx.x & 31;
    int wid  = threadIdx.x >> 5;
    int v = (i < N) ? g_deg[i] : 0;
    int x = v;
    #pragma unroll
    for (int off = 1; off < 32; off <<= 1) {
        int y = __shfl_up_sync(0xffffffffu, x, off);
        if (lane >= off) x += y;
    }
    if (lane == 31) wsum[wid] = x;
    __syncthreads();
    if (wid == 0) {
        int w = wsum[lane];
        #pragma unroll
        for (int off = 1; off < 32; off <<= 1) {
            int y = __shfl_up_sync(0xffffffffu, w, off);
            if (lane >= off) w += y;
        }
        wsum[lane] = w;
    }
    __syncthreads();
    int excl = x - v + (wid > 0 ? wsum[wid - 1] : 0);
    if (i < N) g_rowptr[i] = excl;
    if (threadIdx.x == 1023) g_bsum[blockIdx.x] = excl + v;
}

// phase 2: scan block sums (<=64 blocks), write grand total to g_rowptr[N]
__global__ void scan_bsums(int nb, int N) {
    __shared__ int s[64];
    int t = threadIdx.x;  // 64 threads
    int v = (t < nb) ? g_bsum[t] : 0;
    s[t] = v;
    __syncthreads();
    #pragma unroll
    for (int off = 1; off < 64; off <<= 1) {
        int add = (t >= off) ? s[t - off] : 0;
        __syncthreads();
        s[t] += add;
        __syncthreads();
    }
    int incl = s[t];
    if (t < nb) g_bsum[t] = incl - v;
    if (t == 63) g_rowptr[N] = incl;
}

// phase 3: add block offsets, init cursor
__global__ void add_offsets(int N) {
    int i = blockIdx.x * blockDim.x + threadIdx.x;
    if (i < N) {
        int r = g_rowptr[i] + g_bsum[i >> 10];
        g_rowptr[i] = r;
        g_cursor[i] = r;
    }
}

__global__ void scatter_edges(const int* __restrict__ ei, int E, int Etot) {
    int e = blockIdx.x * blockDim.x + threadIdx.x;
    if (e >= Etot) return;
    int src, dst;
    if (e < E) { src = ei[e]; dst = ei[E + e]; }
    else       { src = dst = e - E; }
    int pos = atomicAdd(&g_cursor[dst], 1);
    g_csr_src[pos] = src;
    g_csr_eid[pos] = e;
}

// ---------------- encoder: h0 = x @ W(16x128) + b ----------------
__global__ void encoder_kernel(const float* __restrict__ x,
                               const float* __restrict__ W,
                               const float* __restrict__ b, int N) {
    int n = blockIdx.x;
    if (n >= N) return;
    int t = threadIdx.x;  // 128 threads
    __shared__ float xs[16];
    if (t < 16) xs[t] = x[n * 16 + t];
    __syncthreads();
    float acc = b[t];
    #pragma unroll
    for (int k = 0; k < 16; k++) acc = fmaf(xs[k], W[k * 128 + t], acc);
    g_h0[n * 128 + t] = acc;
}

// ---------------- FFMA2 SGEMM: C[M, TWO?256:128] = A[M,128] @ [B0|B1] + bias ----------------
// Each CTA: 128-row x (TWO?256:128)-col tile. Thread (tx,ty): rows ty*8..+7,
// column pairs {2tx+32jj, 2tx+32jj+1}. A values duplicated in smem as (a,a) 64-bit
// pairs so a-operand of fma.rn.f32x2 is one LDS.64; b-operand is a natural column pair.
template <int TWO, int RELU>
__global__ __launch_bounds__(256, 1) void sgemm2(
    const float* __restrict__ A,
    const float* __restrict__ B0, const float* __restrict__ B1,
    const float* __restrict__ bias0, const float* __restrict__ bias1,
    float* __restrict__ C, int ldc, int M)
{
    const int NJ = TWO ? 8 : 4;
    __shared__ float As2[8][258];              // duplicated A: As2[k][2m]=As2[k][2m+1]=A[m][k]
    __shared__ float Bs[8][TWO ? 256 : 128];

    int tid = threadIdx.x;
    int m0  = blockIdx.x * 128;
    int tx = tid & 15, ty = tid >> 4;
    int cm = ty * 8;

    unsigned long long acc[8][NJ];
    #pragma unroll
    for (int i = 0; i < 8; i++)
        #pragma unroll
        for (int j = 0; j < NJ; j++) acc[i][j] = 0ull;

    int arow = tid >> 1;
    int acol = (tid & 1) * 4;
    int brow = tid >> 5;
    int bcol = (tid & 31) * 4;

    for (int k0 = 0; k0 < 128; k0 += 8) {
        float4 av = make_float4(0.f, 0.f, 0.f, 0.f);
        if (m0 + arow < M)
            av = *(const float4*)(A + (size_t)(m0 + arow) * 128 + k0 + acol);
        *(float2*)&As2[acol + 0][2 * arow] = make_float2(av.x, av.x);
        *(float2*)&As2[acol + 1][2 * arow] = make_float2(av.y, av.y);
        *(float2*)&As2[acol + 2][2 * arow] = make_float2(av.z, av.z);
        *(float2*)&As2[acol + 3][2 * arow] = make_float2(av.w, av.w);

        *(float4*)(&Bs[brow][bcol]) = *(const float4*)(B0 + (k0 + brow) * 128 + bcol);
        if (TWO)
            *(float4*)(&Bs[brow][128 + bcol]) = *(const float4*)(B1 + (k0 + brow) * 128 + bcol);
        __syncthreads();

        #pragma unroll
        for (int k = 0; k < 8; k++) {
            unsigned long long a2[8], b2[NJ];
            #pragma unroll
            for (int i = 0; i < 8; i++)
                a2[i] = *(const unsigned long long*)&As2[k][2 * (cm + i)];
            #pragma unroll
            for (int j = 0; j < NJ; j++)
                b2[j] = *(const unsigned long long*)&Bs[k][2 * tx + 32 * j];
            #pragma unroll
            for (int i = 0; i < 8; i++)
                #pragma unroll
                for (int j = 0; j < NJ; j++)
                    ffma2(acc[i][j], a2[i], b2[j]);
        }
        __syncthreads();
    }

    // epilogue
    float2 bb[NJ];
    #pragma unroll
    for (int j = 0; j < NJ; j++) {
        int col = 2 * tx + 32 * j;
        const float* bp = (TWO && j >= 4) ? (bias1 + col - 128) : (bias0 + col);
        bb[j] = make_float2(bp[0], bp[1]);
    }
    #pragma unroll
    for (int i = 0; i < 8; i++) {
        int m = m0 + cm + i;
        if (m < M) {
            #pragma unroll
            for (int j = 0; j < NJ; j++) {
                int col = 2 * tx + 32 * j;
                float2 v = unpack2(acc[i][j]);
                v.x += bb[j].x; v.y += bb[j].y;
                if (RELU) { v.x = fmaxf(v.x, 0.f); v.y = fmaxf(v.y, 0.f); }
                *(float2*)(C + (size_t)m * ldc + col) = v;
            }
        }
    }
}

// ---------------- GATv2 aggregation: one warp per destination node ----------------
// Lane layout: head h = lane>>3, each lane owns 4 channels (float4).
// Per edge: 1x LDG.128 of xl[src] slice, 3-shuffle 8-lane reduce per head.
__global__ void gat_aggregate(const float* __restrict__ xlr,
                              const float* __restrict__ att,  // [4*32]
                              const float* __restrict__ bo,   // [128]
                              float* __restrict__ hout,       // [N,128]
                              float* __restrict__ alpha,      // [Etot,4] (raw ex)
                              int N, int do_relu)
{
    int warp = (blockIdx.x * blockDim.x + threadIdx.x) >> 5;
    int lane = threadIdx.x & 31;
    if (warp >= N) return;

    int h = lane >> 3;
    int q = lane & 7;
    int co = h * 32 + q * 4;

    float4 xr4 = *(const float4*)(xlr + (size_t)warp * 256 + 128 + co);
    float4 at4 = *(const float4*)(att + co);
    float4 acc = make_float4(0.f, 0.f, 0.f, 0.f);
    float  D   = 0.f;

    int beg = g_rowptr[warp], end = g_rowptr[warp + 1];
    for (int i = beg; i < end; i++) {
        int src = g_csr_src[i];
        float4 xv = *(const float4*)(xlr + (size_t)src * 256 + co);
        float ex0, ex1, ex2, ex3;
        {
            float e0 = xv.x + xr4.x; e0 = fmaxf(e0, 0.2f * e0);  // leaky_relu(0.2)
            float e1 = xv.y + xr4.y; e1 = fmaxf(e1, 0.2f * e1);
            float e2 = xv.z + xr4.z; e2 = fmaxf(e2, 0.2f * e2);
            float e3 = xv.w + xr4.w; e3 = fmaxf(e3, 0.2f * e3);
            float s = e0 * at4.x;
            s = fmaf(e1, at4.y, s);
            s = fmaf(e2, at4.z, s);
            s = fmaf(e3, at4.w, s);
            s += __shfl_xor_sync(0xffffffffu, s, 1);
            s += __shfl_xor_sync(0xffffffffu, s, 2);
            s += __shfl_xor_sync(0xffffffffu, s, 4);
            float ex = __expf(s);          // scores << 1 -> max-subtraction unnecessary
            D += ex;
            acc.x = fmaf(ex, xv.x, acc.x);
            acc.y = fmaf(ex, xv.y, acc.y);
            acc.z = fmaf(ex, xv.z, acc.z);
            acc.w = fmaf(ex, xv.w, acc.w);
            ex0 = __shfl_sync(0xffffffffu, ex, 0);
            ex1 = __shfl_sync(0xffffffffu, ex, 8);
            ex2 = __shfl_sync(0xffffffffu, ex, 16);
            ex3 = __shfl_sync(0xffffffffu, ex, 24);
        }
        if (lane == 0) {
            int eid = g_csr_eid[i];
            *(float4*)(alpha + (size_t)eid * 4) = make_float4(ex0, ex1, ex2, ex3);
        }
    }

    if (q == 0) g_denom[(size_t)warp * 4 + h] = D;
    float invD = 1.f / D;
    float4 b4 = *(const float4*)(bo + co);
    float4 o;
    o.x = acc.x * invD + b4.x;
    o.y = acc.y * invD + b4.y;
    o.z = acc.z * invD + b4.z;
    o.w = acc.w * invD + b4.w;
    if (do_relu) {
        o.x = fmaxf(o.x, 0.f); o.y = fmaxf(o.y, 0.f);
        o.z = fmaxf(o.z, 0.f); o.w = fmaxf(o.w, 0.f);
    }
    *(float4*)(hout + (size_t)warp * 128 + co) = o;
}

__global__ void normalize_alpha(const int* __restrict__ ei,
                                float* __restrict__ alpha, int E, int Etot)
{
    int e = blockIdx.x * blockDim.x + threadIdx.x;
    if (e >= Etot) return;
    int dst = (e < E) ? ei[E + e] : (e - E);
    float4 a = *(float4*)(alpha + (size_t)e * 4);
    float4 d = *(const float4*)(g_denom + (size_t)dst * 4);
    a.x /= d.x; a.y /= d.y; a.z /= d.z; a.w /= d.w;
    *(float4*)(alpha + (size_t)e * 4) = a;
}

// ---------------- final: probs = sigmoid(t @ W2 + b2), warp per node ----------------
__global__ void final_kernel(const float* __restrict__ t,
                             const float* __restrict__ W2,
                             const float* __restrict__ b2,
                             float* __restrict__ probs, int N)
{
    int warp = (blockIdx.x * blockDim.x + threadIdx.x) >> 5;
    int lane = threadIdx.x & 31;
    if (warp >= N) return;
    const float* row = t + (size_t)warp * 128;
    float s = 0.f;
    #pragma unroll
    for (int j = 0; j < 4; j++)
        s = fmaf(row[j * 32 + lane], W2[j * 32 + lane], s);
    #pragma unroll
    for (int off = 16; off > 0; off >>= 1)
        s += __shfl_xor_sync(0xffffffffu, s, off);
    if (lane == 0) {
        float logit = s + b2[0];
        probs[warp] = 1.f / (1.f + __expf(-logit));
    }
}

// ---------------- launch ----------------
extern "C" void kernel_launch(void* const* d_in, const int* in_sizes, int n_in,
                              void* d_out, int out_size)
{
    const float* x      = (const float*)d_in[0];
    const int*   ei     = (const int*)  d_in[1];
    const float* enc_W  = (const float*)d_in[4];
    const float* enc_b  = (const float*)d_in[5];
    const float* g1_Wl  = (const float*)d_in[6];
    const float* g1_bl  = (const float*)d_in[7];
    const float* g1_Wr  = (const float*)d_in[8];
    const float* g1_br  = (const float*)d_in[9];
    const float* g1_att = (const float*)d_in[10];
    const float* g1_bo  = (const float*)d_in[11];
    const float* g2_Wl  = (const float*)d_in[12];
    const float* g2_bl  = (const float*)d_in[13];
    const float* g2_Wr  = (const float*)d_in[14];
    const float* g2_br  = (const float*)d_in[15];
    const float* g2_att = (const float*)d_in[16];
    const float* g2_bo  = (const float*)d_in[17];
    const float* mlp_W1 = (const float*)d_in[18];
    const float* mlp_b1 = (const float*)d_in[19];
    const float* mlp_W2 = (const float*)d_in[20];
    const float* mlp_b2 = (const float*)d_in[21];

    int N    = in_sizes[0] / 16;
    int E    = in_sizes[1] / 2;
    int Etot = E + N;

    float *h0, *h1, *h2, *xlr, *tb, *fb;
    int* degp;
    cudaGetSymbolAddress((void**)&h0,   g_h0);
    cudaGetSymbolAddress((void**)&h1,   g_h1);
    cudaGetSymbolAddress((void**)&h2,   g_h2);
    cudaGetSymbolAddress((void**)&xlr,  g_xlr);
    cudaGetSymbolAddress((void**)&tb,   g_t);
    cudaGetSymbolAddress((void**)&fb,   g_alpha_fb);
    cudaGetSymbolAddress((void**)&degp, g_deg);

    float* probs = (float*)d_out;
    float* alpha1;
    float* alpha2;
    if (out_size >= N + 8 * Etot) {
        alpha1 = probs + N;
        alpha2 = alpha1 + (size_t)4 * Etot;
    } else {
        alpha1 = fb;
        alpha2 = fb;
    }

    int eb = (Etot + 255) / 256;
    int nb = (N + 255) / 256;
    int wb = (N * 32 + 255) / 256;       // warp-per-node grids
    int sb = (N + 1023) / 1024;          // scan blocks (<=64)
    dim3 gg((N + 127) / 128);

    // CSR build (identical every replay; deterministic work per call)
    cudaMemsetAsync(degp, 0, (size_t)N * sizeof(int));
    build_deg<<<eb, 256>>>(ei, E, Etot);
    scan_blocks<<<sb, 1024>>>(N);
    scan_bsums<<<1, 64>>>(sb, N);
    add_offsets<<<nb, 256>>>(N);
    scatter_edges<<<eb, 256>>>(ei, E, Etot);

    // encoder
    encoder_kernel<<<N, 128>>>(x, enc_W, enc_b, N);

    // GAT layer 1 (fused Wl|Wr GEMM -> xlr)
    sgemm2<1, 0><<<gg, 256>>>(h0, g1_Wl, g1_Wr, g1_bl, g1_br, xlr, 256, N);
    gat_aggregate<<<wb, 256>>>(xlr, g1_att, g1_bo, h1, alpha1, N, 1);
    normalize_alpha<<<eb, 256>>>(ei, alpha1, E, Etot);

    // GAT layer 2
    sgemm2<1, 0><<<gg, 256>>>(h1, g2_Wl, g2_Wr, g2_bl, g2_br, xlr, 256, N);
    gat_aggregate<<<wb, 256>>>(xlr, g2_att, g2_bo, h2, alpha2, N, 0);
    normalize_alpha<<<eb, 256>>>(ei, alpha2, E, Etot);

    // MLP head
    sgemm2<0, 1><<<gg, 256>>>(h2, mlp_W1, mlp_W1, mlp_b1, mlp_b1, tb, 128, N);
    final_kernel<<<wb, 256>>>(tb, mlp_W2, mlp_b2, probs, N);
}

// round 6
// speedup vs baseline: 1.7645x; 1.3998x over previous
#include <cuda_runtime.h>
#include <cuda_bf16.h>
#include <math.h>
#include <stdint.h>

#define MAXN 50000
#define MAXE 800000
#define MAXET (MAXE + MAXN)

// ---------------- static scratch (no allocation allowed) ----------------
__device__ float g_h0[MAXN * 128];     // encoder output
__device__ float g_h1[MAXN * 128];     // layer1 output
__device__ float g_h2[MAXN * 128];     // layer2 output
__device__ float g_xlr[MAXN * 256];    // xl | xr, row stride 256
__device__ float g_t[MAXN * 128];      // relu(h2@W1+b1)
__device__ float g_denom[MAXN * 4];    // per-node per-head softmax denominator
__device__ int   g_deg[MAXN];
__device__ int   g_rowptr[MAXN + 1];
__device__ int   g_cursor[MAXN];
__device__ int   g_bsum[64];
__device__ int2  g_csr[MAXET];         // (src, eid) packed
__device__ float g_alpha_fb[MAXET * 4];
// bf16-split transposed weights: [set][n*128+k]; sets 0,1 are 256-wide, set 2 is 128-wide
__device__ __nv_bfloat16 g_bhi[3][256 * 128];
__device__ __nv_bfloat16 g_blo[3][256 * 128];

// ---------------- HMMA helper (sm_80 PTX, valid under compute_103) ----------------
__device__ __forceinline__ void mma16816(float* d, const uint32_t* a, const uint32_t* b) {
    asm volatile(
        "mma.sync.aligned.m16n8k16.row.col.f32.bf16.bf16.f32 "
        "{%0,%1,%2,%3}, {%4,%5,%6,%7}, {%8,%9}, {%0,%1,%2,%3};"
        : "+f"(d[0]), "+f"(d[1]), "+f"(d[2]), "+f"(d[3])
        : "r"(a[0]), "r"(a[1]), "r"(a[2]), "r"(a[3]), "r"(b[0]), "r"(b[1]));
}

// ---------------- CSR construction ----------------
__global__ void build_deg(const int* __restrict__ ei, int E, int Etot) {
    int e = blockIdx.x * blockDim.x + threadIdx.x;
    if (e >= Etot) return;
    int dst = (e < E) ? ei[E + e] : (e - E);
    atomicAdd(&g_deg[dst], 1);
}

__global__ void scan_blocks(int N) {
    __shared__ int wsum[32];
    int i = blockIdx.x * 1024 + threadIdx.x;
    int lane = threadIdx.x & 31;
    int wid  = threadIdx.x >> 5;
    int v = (i < N) ? g_deg[i] : 0;
    int x = v;
    #pragma unroll
    for (int off = 1; off < 32; off <<= 1) {
        int y = __shfl_up_sync(0xffffffffu, x, off);
        if (lane >= off) x += y;
    }
    if (lane == 31) wsum[wid] = x;
    __syncthreads();
    if (wid == 0) {
        int w = wsum[lane];
        #pragma unroll
        for (int off = 1; off < 32; off <<= 1) {
            int y = __shfl_up_sync(0xffffffffu, w, off);
            if (lane >= off) w += y;
        }
        wsum[lane] = w;
    }
    __syncthreads();
    int excl = x - v + (wid > 0 ? wsum[wid - 1] : 0);
    if (i < N) g_rowptr[i] = excl;
    if (threadIdx.x == 1023) g_bsum[blockIdx.x] = excl + v;
}

__global__ void scan_bsums(int nb, int N) {
    __shared__ int s[64];
    int t = threadIdx.x;  // 64 threads
    int v = (t < nb) ? g_bsum[t] : 0;
    s[t] = v;
    __syncthreads();
    #pragma unroll
    for (int off = 1; off < 64; off <<= 1) {
        int add = (t >= off) ? s[t - off] : 0;
        __syncthreads();
        s[t] += add;
        __syncthreads();
    }
    int incl = s[t];
    if (t < nb) g_bsum[t] = incl - v;
    if (t == 63) g_rowptr[N] = incl;
}

__global__ void add_offsets(int N) {
    int i = blockIdx.x * blockDim.x + threadIdx.x;
    if (i < N) {
        int r = g_rowptr[i] + g_bsum[i >> 10];
        g_rowptr[i] = r;
        g_cursor[i] = r;
    }
}

__global__ void scatter_edges(const int* __restrict__ ei, int E, int Etot) {
    int e = blockIdx.x * blockDim.x + threadIdx.x;
    if (e >= Etot) return;
    int src, dst;
    if (e < E) { src = ei[e]; dst = ei[E + e]; }
    else       { src = dst = e - E; }
    int pos = atomicAdd(&g_cursor[dst], 1);
    g_csr[pos] = make_int2(src, e);
}

// ---------------- weight prep: transpose + bf16 hi/lo split ----------------
// Bt[n][k] = W[k][n]; n<128 from Wl, n>=128 from Wr. NT = 256 (fused) or 128.
__global__ void prep_w(const float* __restrict__ Wl, const float* __restrict__ Wr,
                       __nv_bfloat16* __restrict__ hi, __nv_bfloat16* __restrict__ lo,
                       int NT) {
    int i = blockIdx.x * blockDim.x + threadIdx.x;
    if (i >= NT * 128) return;
    int n = i >> 7, k = i & 127;
    float w = (n < 128) ? Wl[k * 128 + n] : Wr[k * 128 + (n - 128)];
    __nv_bfloat16 h = __float2bfloat16(w);
    hi[i] = h;
    lo[i] = __float2bfloat16(w - __bfloat162float(h));
}

// ---------------- encoder: h0 = x @ W(16x128) + b ----------------
__global__ void encoder_kernel(const float* __restrict__ x,
                               const float* __restrict__ W,
                               const float* __restrict__ b, int N) {
    int n = blockIdx.x;
    if (n >= N) return;
    int t = threadIdx.x;  // 128 threads
    __shared__ float xs[16];
    if (t < 16) xs[t] = x[n * 16 + t];
    __syncthreads();
    float acc = b[t];
    #pragma unroll
    for (int k = 0; k < 16; k++) acc = fmaf(xs[k], W[k * 128 + t], acc);
    g_h0[n * 128 + t] = acc;
}

// ---------------- HMMA bf16-split GEMM ----------------
// C[M, gy*128 .. +128] = A[M,128](fp32) @ Bt^T + bias, via A1B1 + A2B1 + A1B2.
// CTA = 128 rows x 128 cols. 8 warps in 4x2 (m x n); warp tile 32x64.
// smem: padded stride 136 bf16 -> LDS.32 fragment loads are conflict-free.
#define SSTRIDE 136
template <int RELU>
__global__ __launch_bounds__(256, 1)
void gemm_hmma(const float* __restrict__ A,
               const __nv_bfloat16* __restrict__ Bhi,
               const __nv_bfloat16* __restrict__ Blo,
               const float* __restrict__ bias0, const float* __restrict__ bias1,
               float* __restrict__ C, int ldc, int M)
{
    extern __shared__ __nv_bfloat16 smem[];
    __nv_bfloat16* As1 = smem;                     // 128 x 136
    __nv_bfloat16* As2 = As1 + 128 * SSTRIDE;
    __nv_bfloat16* Bs1 = As2 + 128 * SSTRIDE;
    __nv_bfloat16* Bs2 = Bs1 + 128 * SSTRIDE;

    int tid = threadIdx.x;
    int wid = tid >> 5, lane = tid & 31;
    int m0 = blockIdx.x * 128;
    int gy = blockIdx.y;
    const float* bias = gy ? bias1 : bias0;
    const __nv_bfloat16* Bh = Bhi + (size_t)gy * 128 * 128;
    const __nv_bfloat16* Bl = Blo + (size_t)gy * 128 * 128;
    float* Cg = C + gy * 128;

    // A: fp32 -> bf16 hi/lo into padded smem (float4 per iter -> 4 bf16 = 8B store)
    #pragma unroll
    for (int it = 0; it < 16; it++) {
        int j = tid + it * 256;            // 0..4095 float4s
        int r = j >> 5, c4 = (j & 31) * 4;
        int m = m0 + r;
        float4 av = (m < M) ? *(const float4*)(A + (size_t)m * 128 + c4)
                            : make_float4(0.f, 0.f, 0.f, 0.f);
        __nv_bfloat16 h[4], l[4];
        h[0] = __float2bfloat16(av.x); l[0] = __float2bfloat16(av.x - __bfloat162float(h[0]));
        h[1] = __float2bfloat16(av.y); l[1] = __float2bfloat16(av.y - __bfloat162float(h[1]));
        h[2] = __float2bfloat16(av.z); l[2] = __float2bfloat16(av.z - __bfloat162float(h[2]));
        h[3] = __float2bfloat16(av.w); l[3] = __float2bfloat16(av.w - __bfloat162float(h[3]));
        uint2 ph, pl;
        ph.x = ((uint32_t)__bfloat16_as_ushort(h[1]) << 16) | __bfloat16_as_ushort(h[0]);
        ph.y = ((uint32_t)__bfloat16_as_ushort(h[3]) << 16) | __bfloat16_as_ushort(h[2]);
        pl.x = ((uint32_t)__bfloat16_as_ushort(l[1]) << 16) | __bfloat16_as_ushort(l[0]);
        pl.y = ((uint32_t)__bfloat16_as_ushort(l[3]) << 16) | __bfloat16_as_ushort(l[2]);
        *(uint2*)(As1 + r * SSTRIDE + c4) = ph;
        *(uint2*)(As2 + r * SSTRIDE + c4) = pl;
    }
    // B: bf16 [128][128] row-major -> padded smem (uint4 = 8 bf16 per iter)
    #pragma unroll
    for (int it = 0; it < 8; it++) {
        int j = tid + it * 256;            // 0..2047 uint4s
        int n = j >> 4, k8 = (j & 15) * 8;
        *(uint4*)(Bs1 + n * SSTRIDE + k8) = *(const uint4*)(Bh + (size_t)n * 128 + k8);
        *(uint4*)(Bs2 + n * SSTRIDE + k8) = *(const uint4*)(Bl + (size_t)n * 128 + k8);
    }
    __syncthreads();

    int wm = wid >> 1;      // 0..3 -> m offset wm*32
    int wn = wid & 1;       // 0..1 -> n offset wn*64
    int lr = lane >> 2;     // 0..7
    int lc = lane & 3;      // 0..3

    float acc[2][8][4];
    #pragma unroll
    for (int mi = 0; mi < 2; mi++)
        #pragma unroll
        for (int nj = 0; nj < 8; nj++)
            #pragma unroll
            for (int q = 0; q < 4; q++) acc[mi][nj][q] = 0.f;

    const __nv_bfloat16* Apt[3] = {As1, As2, As1};
    const __nv_bfloat16* Bpt[3] = {Bs1, Bs1, Bs2};

    #pragma unroll
    for (int t = 0; t < 3; t++) {
        const __nv_bfloat16* Ap = Apt[t];
        const __nv_bfloat16* Bp = Bpt[t];
        #pragma unroll
        for (int kk = 0; kk < 8; kk++) {
            int k0 = kk * 16 + lc * 2;
            uint32_t a[2][4], b[8][2];
            #pragma unroll
            for (int mi = 0; mi < 2; mi++) {
                int m = wm * 32 + mi * 16 + lr;
                a[mi][0] = *(const uint32_t*)(Ap + m * SSTRIDE + k0);
                a[mi][1] = *(const uint32_t*)(Ap + (m + 8) * SSTRIDE + k0);
                a[mi][2] = *(const uint32_t*)(Ap + m * SSTRIDE + k0 + 8);
                a[mi][3] = *(const uint32_t*)(Ap + (m + 8) * SSTRIDE + k0 + 8);
            }
            #pragma unroll
            for (int nj = 0; nj < 8; nj++) {
                int n = wn * 64 + nj * 8 + lr;
                b[nj][0] = *(const uint32_t*)(Bp + n * SSTRIDE + k0);
                b[nj][1] = *(const uint32_t*)(Bp + n * SSTRIDE + k0 + 8);
            }
            #pragma unroll
            for (int mi = 0; mi < 2; mi++)
                #pragma unroll
                for (int nj = 0; nj < 8; nj++)
                    mma16816(acc[mi][nj], a[mi], b[nj]);
        }
    }

    // epilogue: d0,d1 -> (row, col..col+1); d2,d3 -> (row+8, col..col+1)
    #pragma unroll
    for (int nj = 0; nj < 8; nj++) {
        int col = wn * 64 + nj * 8 + lc * 2;
        float b0 = bias[col], b1 = bias[col + 1];
        #pragma unroll
        for (int mi = 0; mi < 2; mi++) {
            int m = m0 + wm * 32 + mi * 16 + lr;
            float2 v0, v1;
            v0.x = acc[mi][nj][0] + b0; v0.y = acc[mi][nj][1] + b1;
            v1.x = acc[mi][nj][2] + b0; v1.y = acc[mi][nj][3] + b1;
            if (RELU) {
                v0.x = fmaxf(v0.x, 0.f); v0.y = fmaxf(v0.y, 0.f);
                v1.x = fmaxf(v1.x, 0.f); v1.y = fmaxf(v1.y, 0.f);
            }
            if (m < M)     *(float2*)(Cg + (size_t)m * ldc + col) = v0;
            if (m + 8 < M) *(float2*)(Cg + (size_t)(m + 8) * ldc + col) = v1;
        }
    }
}

// ---------------- GATv2 aggregation: one warp per destination node ----------------
__global__ void gat_aggregate(const float* __restrict__ xlr,
                              const float* __restrict__ att,  // [4*32]
                              const float* __restrict__ bo,   // [128]
                              float* __restrict__ hout,       // [N,128]
                              float* __restrict__ alpha,      // [Etot,4] (raw ex)
                              int N, int do_relu)
{
    int warp = (blockIdx.x * blockDim.x + threadIdx.x) >> 5;
    int lane = threadIdx.x & 31;
    if (warp >= N) return;

    int h = lane >> 3;
    int q = lane & 7;
    int co = h * 32 + q * 4;

    float4 xr4 = *(const float4*)(xlr + (size_t)warp * 256 + 128 + co);
    float4 at4 = *(const float4*)(att + co);
    float4 acc = make_float4(0.f, 0.f, 0.f, 0.f);
    float  D   = 0.f;

    int beg = g_rowptr[warp], end = g_rowptr[warp + 1];
    for (int i = beg; i < end; i++) {
        int2 se = g_csr[i];
        int src = se.x;
        float4 xv = *(const float4*)(xlr + (size_t)src * 256 + co);
        float e0 = xv.x + xr4.x; e0 = fmaxf(e0, 0.2f * e0);  // leaky_relu(0.2)
        float e1 = xv.y + xr4.y; e1 = fmaxf(e1, 0.2f * e1);
        float e2 = xv.z + xr4.z; e2 = fmaxf(e2, 0.2f * e2);
        float e3 = xv.w + xr4.w; e3 = fmaxf(e3, 0.2f * e3);
        float s = e0 * at4.x;
        s = fmaf(e1, at4.y, s);
        s = fmaf(e2, at4.z, s);
        s = fmaf(e3, at4.w, s);
        s += __shfl_xor_sync(0xffffffffu, s, 1);
        s += __shfl_xor_sync(0xffffffffu, s, 2);
        s += __shfl_xor_sync(0xffffffffu, s, 4);
        float ex = __expf(s);              // scores << 1 -> no max-subtraction needed
        D += ex;
        acc.x = fmaf(ex, xv.x, acc.x);
        acc.y = fmaf(ex, xv.y, acc.y);
        acc.z = fmaf(ex, xv.z, acc.z);
        acc.w = fmaf(ex, xv.w, acc.w);
        float ex0 = __shfl_sync(0xffffffffu, ex, 0);
        float ex1 = __shfl_sync(0xffffffffu, ex, 8);
        float ex2 = __shfl_sync(0xffffffffu, ex, 16);
        float ex3 = __shfl_sync(0xffffffffu, ex, 24);
        if (lane == 0) {
            *(float4*)(alpha + (size_t)se.y * 4) = make_float4(ex0, ex1, ex2, ex3);
        }
    }

    if (q == 0) g_denom[(size_t)warp * 4 + h] = D;
    float invD = 1.f / D;
    float4 b4 = *(const float4*)(bo + co);
    float4 o;
    o.x = acc.x * invD + b4.x;
    o.y = acc.y * invD + b4.y;
    o.z = acc.z * invD + b4.z;
    o.w = acc.w * invD + b4.w;
    if (do_relu) {
        o.x = fmaxf(o.x, 0.f); o.y = fmaxf(o.y, 0.f);
        o.z = fmaxf(o.z, 0.f); o.w = fmaxf(o.w, 0.f);
    }
    *(float4*)(hout + (size_t)warp * 128 + co) = o;
}

__global__ void normalize_alpha(const int* __restrict__ ei,
                                float* __restrict__ alpha, int E, int Etot)
{
    int e = blockIdx.x * blockDim.x + threadIdx.x;
    if (e >= Etot) return;
    int dst = (e < E) ? ei[E + e] : (e - E);
    float4 a = *(float4*)(alpha + (size_t)e * 4);
    float4 d = *(const float4*)(g_denom + (size_t)dst * 4);
    a.x /= d.x; a.y /= d.y; a.z /= d.z; a.w /= d.w;
    *(float4*)(alpha + (size_t)e * 4) = a;
}

// ---------------- final: probs = sigmoid(t @ W2 + b2), warp per node ----------------
__global__ void final_kernel(const float* __restrict__ t,
                             const float* __restrict__ W2,
                             const float* __restrict__ b2,
                             float* __restrict__ probs, int N)
{
    int warp = (blockIdx.x * blockDim.x + threadIdx.x) >> 5;
    int lane = threadIdx.x & 31;
    if (warp >= N) return;
    const float* row = t + (size_t)warp * 128;
    float s = 0.f;
    #pragma unroll
    for (int j = 0; j < 4; j++)
        s = fmaf(row[j * 32 + lane], W2[j * 32 + lane], s);
    #pragma unroll
    for (int off = 16; off > 0; off >>= 1)
        s += __shfl_xor_sync(0xffffffffu, s, off);
    if (lane == 0) {
        float logit = s + b2[0];
        probs[warp] = 1.f / (1.f + __expf(-logit));
    }
}

// ---------------- launch ----------------
extern "C" void kernel_launch(void* const* d_in, const int* in_sizes, int n_in,
                              void* d_out, int out_size)
{
    const float* x      = (const float*)d_in[0];
    const int*   ei     = (const int*)  d_in[1];
    const float* enc_W  = (const float*)d_in[4];
    const float* enc_b  = (const float*)d_in[5];
    const float* g1_Wl  = (const float*)d_in[6];
    const float* g1_bl  = (const float*)d_in[7];
    const float* g1_Wr  = (const float*)d_in[8];
    const float* g1_br  = (const float*)d_in[9];
    const float* g1_att = (const float*)d_in[10];
    const float* g1_bo  = (const float*)d_in[11];
    const float* g2_Wl  = (const float*)d_in[12];
    const float* g2_bl  = (const float*)d_in[13];
    const float* g2_Wr  = (const float*)d_in[14];
    const float* g2_br  = (const float*)d_in[15];
    const float* g2_att = (const float*)d_in[16];
    const float* g2_bo  = (const float*)d_in[17];
    const float* mlp_W1 = (const float*)d_in[18];
    const float* mlp_b1 = (const float*)d_in[19];
    const float* mlp_W2 = (const float*)d_in[20];
    const float* mlp_b2 = (const float*)d_in[21];

    int N    = in_sizes[0] / 16;
    int E    = in_sizes[1] / 2;
    int Etot = E + N;

    float *h0, *h1, *h2, *xlr, *tb, *fb;
    int* degp;
    __nv_bfloat16 *bhi, *blo;
    cudaGetSymbolAddress((void**)&h0,   g_h0);
    cudaGetSymbolAddress((void**)&h1,   g_h1);
    cudaGetSymbolAddress((void**)&h2,   g_h2);
    cudaGetSymbolAddress((void**)&xlr,  g_xlr);
    cudaGetSymbolAddress((void**)&tb,   g_t);
    cudaGetSymbolAddress((void**)&fb,   g_alpha_fb);
    cudaGetSymbolAddress((void**)&degp, g_deg);
    cudaGetSymbolAddress((void**)&bhi,  g_bhi);
    cudaGetSymbolAddress((void**)&blo,  g_blo);
    const int WSTRIDE = 256 * 128;

    float* probs = (float*)d_out;
    float* alpha1;
    float* alpha2;
    if (out_size >= N + 8 * Etot) {
        alpha1 = probs + N;
        alpha2 = alpha1 + (size_t)4 * Etot;
    } else {
        alpha1 = fb;
        alpha2 = fb;
    }

    int eb = (Etot + 255) / 256;
    int nb = (N + 255) / 256;
    int wb = (N * 32 + 255) / 256;       // warp-per-node grids
    int sb = (N + 1023) / 1024;          // scan blocks (<=64)

    const size_t SMEM = 4 * 128 * SSTRIDE * sizeof(__nv_bfloat16);  // 139264 B
    cudaFuncSetAttribute(gemm_hmma<0>, cudaFuncAttributeMaxDynamicSharedMemorySize, (int)SMEM);
    cudaFuncSetAttribute(gemm_hmma<1>, cudaFuncAttributeMaxDynamicSharedMemorySize, (int)SMEM);
    dim3 gg2((N + 127) / 128, 2);
    dim3 gg1((N + 127) / 128, 1);

    // weight prep (tiny; once per graph replay)
    prep_w<<<(256 * 128 + 255) / 256, 256>>>(g1_Wl, g1_Wr, bhi + 0 * WSTRIDE, blo + 0 * WSTRIDE, 256);
    prep_w<<<(256 * 128 + 255) / 256, 256>>>(g2_Wl, g2_Wr, bhi + 1 * WSTRIDE, blo + 1 * WSTRIDE, 256);
    prep_w<<<(128 * 128 + 255) / 256, 256>>>(mlp_W1, mlp_W1, bhi + 2 * WSTRIDE, blo + 2 * WSTRIDE, 128);

    // CSR build
    cudaMemsetAsync(degp, 0, (size_t)N * sizeof(int));
    build_deg<<<eb, 256>>>(ei, E, Etot);
    scan_blocks<<<sb, 1024>>>(N);
    scan_bsums<<<1, 64>>>(sb, N);
    add_offsets<<<nb, 256>>>(N);
    scatter_edges<<<eb, 256>>>(ei, E, Etot);

    // encoder
    encoder_kernel<<<N, 128>>>(x, enc_W, enc_b, N);

    // GAT layer 1 (HMMA fused Wl|Wr GEMM -> xlr)
    gemm_hmma<0><<<gg2, 256, SMEM>>>(h0, bhi + 0 * WSTRIDE, blo + 0 * WSTRIDE,
                                     g1_bl, g1_br, xlr, 256, N);
    gat_aggregate<<<wb, 256>>>(xlr, g1_att, g1_bo, h1, alpha1, N, 1);
    normalize_alpha<<<eb, 256>>>(ei, alpha1, E, Etot);

    // GAT layer 2
    gemm_hmma<0><<<gg2, 256, SMEM>>>(h1, bhi + 1 * WSTRIDE, blo + 1 * WSTRIDE,
                                     g2_bl, g2_br, xlr, 256, N);
    gat_aggregate<<<wb, 256>>>(xlr, g2_att, g2_bo, h2, alpha2, N, 0);
    normalize_alpha<<<eb, 256>>>(ei, alpha2, E, Etot);

    // MLP head
    gemm_hmma<1><<<gg1, 256, SMEM>>>(h2, bhi + 2 * WSTRIDE, blo + 2 * WSTRIDE,
                                     mlp_b1, mlp_b1, tb, 128, N);
    final_kernel<<<wb, 256>>>(tb, mlp_W2, mlp_b2, probs, N);
}